// round 1
// baseline (speedup 1.0000x reference)
#include <cuda_runtime.h>

#define GN     41
#define GC     32
#define GF     128
#define PLANE  (GN*GN*GN)        // 68921 cells
#define TOTAL  (PLANE*GC)        // 2205472 grid elements

// Transposed grid: [x][y][z][c], c innermost -> one cell = 32 floats = 128B line.
// Stored as float4 so each lane loads 4 channels at once.
__device__ __align__(128) float4 g4buf[PLANE * 8];

// dst[cell*32 + c] = src[c*PLANE + cell]   (cell = (x*41+y)*41+z)
__global__ void transpose_kernel(const float* __restrict__ src) {
    int idx = blockIdx.x * 256 + threadIdx.x;
    if (idx >= TOTAL) return;
    int c    = idx & 31;
    int cell = idx >> 5;
    ((float*)g4buf)[idx] = src[c * PLANE + cell];
}

__device__ __forceinline__ void bspline(float t, float& w0, float& w1, float& w2, float& w3) {
    float t2 = t * t, t3 = t2 * t;
    const float s = 1.0f / 6.0f;
    w0 = s * (1.0f - 3.0f * t + 3.0f * t2 - t3);
    w1 = s * (4.0f - 6.0f * t2 + 3.0f * t3);
    w2 = s * (1.0f + 3.0f * t + 3.0f * t2 - 3.0f * t3);
    w3 = s * t3;
}

__device__ __forceinline__ int clampi(int v) {
    return min(max(v, 0), GN - 1);
}

__device__ __forceinline__ float normu(float v) {
    float n = 0.5f + 0.5f * (v / 5.0f);
    n = fminf(fmaxf(n, 0.0f), 1.0f);
    return n * (float)(GN - 1);
}

// Block = 256 threads = 8 warps, 32 points per block.
// Phase 1 (interp): warp-per-point, 4 points/warp. Lane l: z-tap kk = l>>3,
//   channel-quad ch = l&7. Per (i,j) tap: one coalesced LDG.128 covering
//   4 z-cells x 32 channels (512B contiguous in transposed grid).
// Phase 2 (matmul): warp covers its 4 points x all 128 feats; lane owns feats
//   [lane*4, lane*4+4). Coalesced float4 stores.
__global__ __launch_bounds__(256) void enc_kernel(
    const float* __restrict__ nb,
    const float* __restrict__ encw,
    const float* __restrict__ encb,
    float* __restrict__ out)
{
    __shared__ __align__(16) float ligT[GC][36];    // [channel][point-in-block]
    __shared__ __align__(16) float wS[GC][132];     // [k][feat]

    const int tid  = threadIdx.x;
    const int warp = tid >> 5;
    const int lane = tid & 31;
    const int p0   = blockIdx.x << 5;

    // Stage enc_w transposed: wS[k][f] = encw[f*32 + k]
    #pragma unroll
    for (int e = tid; e < GF * GC; e += 256) {
        wS[e & 31][e >> 5] = encw[e];
    }

    const int kk = lane >> 3;   // which z-tap this lane handles (0..3)
    const int ch = lane & 7;    // which channel-quad (0..7)

    for (int pi = 0; pi < 4; pi++) {
        const int pp = (warp << 2) + pi;     // point index within block
        const int p  = p0 + pp;              // global point

        const float vx = nb[p * 3 + 0];
        const float vy = nb[p * 3 + 1];
        const float vz = nb[p * 3 + 2];

        const float ux = normu(vx), uy = normu(vy), uz = normu(vz);
        const float fbx = floorf(ux), fby = floorf(uy), fbz = floorf(uz);
        const float tx = ux - fbx, ty = uy - fby, tz = uz - fbz;
        const int ibx = (int)fbx, iby = (int)fby, ibz = (int)fbz;

        float wxs[4], wys[4], wz0, wz1, wz2, wz3;
        bspline(tx, wxs[0], wxs[1], wxs[2], wxs[3]);
        bspline(ty, wys[0], wys[1], wys[2], wys[3]);
        bspline(tz, wz0, wz1, wz2, wz3);

        const float myWz = (kk == 0) ? wz0 : (kk == 1) ? wz1 : (kk == 2) ? wz2 : wz3;
        const int  myIz  = clampi(ibz - 1 + kk);
        const int  zpart = myIz * 8 + ch;    // float4 offset within (x,y) row

        int ixs[4], iys[4];
        #pragma unroll
        for (int i = 0; i < 4; i++) {
            ixs[i] = clampi(ibx - 1 + i);
            iys[i] = clampi(iby - 1 + i);
        }

        float ax = 0.0f, ay = 0.0f, az = 0.0f, aw = 0.0f;
        #pragma unroll
        for (int i = 0; i < 4; i++) {
            const int rowx = ixs[i] * GN;
            #pragma unroll
            for (int j = 0; j < 4; j++) {
                const float wij = wxs[i] * wys[j];
                const float w   = wij * myWz;
                const float4 v  = __ldg(&g4buf[(rowx + iys[j]) * (GN * 8) + zpart]);
                ax = fmaf(w, v.x, ax);
                ay = fmaf(w, v.y, ay);
                az = fmaf(w, v.z, az);
                aw = fmaf(w, v.w, aw);
            }
        }

        // Reduce over the 4 z-tap lane groups (lanes l, l^8, l^16, l^24)
        #pragma unroll
        for (int off = 8; off <= 16; off <<= 1) {
            ax += __shfl_xor_sync(0xffffffffu, ax, off);
            ay += __shfl_xor_sync(0xffffffffu, ay, off);
            az += __shfl_xor_sync(0xffffffffu, az, off);
            aw += __shfl_xor_sync(0xffffffffu, aw, off);
        }
        if (lane < 8) {
            ligT[ch * 4 + 0][pp] = ax;
            ligT[ch * 4 + 1][pp] = ay;
            ligT[ch * 4 + 2][pp] = az;
            ligT[ch * 4 + 3][pp] = aw;
        }
    }
    __syncthreads();

    // Matmul: out[p][f] = sum_k lig[p][k] * wS[k][f] + b[f]
    const int pb = warp << 2;   // this warp's 4 points (within block)
    const float4 b4 = *(const float4*)(encb + lane * 4);
    float4 a0 = b4, a1 = b4, a2 = b4, a3 = b4;

    #pragma unroll
    for (int k = 0; k < GC; k++) {
        const float4 lg = *(const float4*)&ligT[k][pb];        // 4 points, broadcast
        const float4 wv = *(const float4*)&wS[k][lane * 4];    // 4 feats, conflict-free
        a0.x = fmaf(lg.x, wv.x, a0.x); a0.y = fmaf(lg.x, wv.y, a0.y);
        a0.z = fmaf(lg.x, wv.z, a0.z); a0.w = fmaf(lg.x, wv.w, a0.w);
        a1.x = fmaf(lg.y, wv.x, a1.x); a1.y = fmaf(lg.y, wv.y, a1.y);
        a1.z = fmaf(lg.y, wv.z, a1.z); a1.w = fmaf(lg.y, wv.w, a1.w);
        a2.x = fmaf(lg.z, wv.x, a2.x); a2.y = fmaf(lg.z, wv.y, a2.y);
        a2.z = fmaf(lg.z, wv.z, a2.z); a2.w = fmaf(lg.z, wv.w, a2.w);
        a3.x = fmaf(lg.w, wv.x, a3.x); a3.y = fmaf(lg.w, wv.y, a3.y);
        a3.z = fmaf(lg.w, wv.z, a3.z); a3.w = fmaf(lg.w, wv.w, a3.w);
    }

    float4* o4 = (float4*)out;
    const int rowbase = (p0 + pb) * (GF / 4) + lane;   // float4 index
    o4[rowbase + 0 * (GF / 4)] = a0;
    o4[rowbase + 1 * (GF / 4)] = a1;
    o4[rowbase + 2 * (GF / 4)] = a2;
    o4[rowbase + 3 * (GF / 4)] = a3;
}

extern "C" void kernel_launch(void* const* d_in, const int* in_sizes, int n_in,
                              void* d_out, int out_size) {
    const float* nb   = nullptr;
    const float* grid = nullptr;
    const float* encw = nullptr;
    const float* encb = nullptr;
    int nbatch = 131072;

    for (int i = 0; i < n_in; i++) {
        switch (in_sizes[i]) {
            case TOTAL:       grid = (const float*)d_in[i]; break;
            case GF * GC:     encw = (const float*)d_in[i]; break;
            case GF:          encb = (const float*)d_in[i]; break;
            default:
                nb = (const float*)d_in[i];
                nbatch = in_sizes[i] / 3;
                break;
        }
    }

    transpose_kernel<<<(TOTAL + 255) / 256, 256>>>(grid);

    const int blocks = nbatch / 32;
    enc_kernel<<<blocks, 256>>>(nb, encw, encb, (float*)d_out);
}

// round 2
// speedup vs baseline: 1.2177x; 1.2177x over previous
#include <cuda_runtime.h>
#include <cuda_fp16.h>

#define GN     41
#define GC     32
#define GF     128
#define PLANE  (GN*GN*GN)        // 68921 cells
#define TOTAL  (PLANE*GC)        // 2205472 grid elements

// Transposed fp16 grid: [x][y][z][c], c innermost. One cell = 32 halves = 64B.
// Indexed as uint2 (4 halves = 4 channels): cell*8 + chquad.
__device__ __align__(128) uint2 g2buf[PLANE * 8];

// Tiled transpose + fp32->fp16 convert. Block handles 64 cells x 32 channels.
// Reads coalesced (64 consecutive cells per channel), writes coalesced (uint).
__global__ __launch_bounds__(256) void transpose_kernel(const float* __restrict__ src) {
    __shared__ float tile[32][65];
    const int cellBase = blockIdx.x * 64;
    const int tid = threadIdx.x;

    const int c_l = tid >> 6;    // 0..3
    const int cl  = tid & 63;    // 0..63
    #pragma unroll
    for (int cc = 0; cc < 8; cc++) {
        const int c    = cc * 4 + c_l;
        const int cell = cellBase + cl;
        tile[c][cl] = (cell < PLANE) ? src[c * PLANE + cell] : 0.0f;
    }
    __syncthreads();

    #pragma unroll
    for (int it = 0; it < 4; it++) {
        const int o   = it * 256 + tid;
        const int cl2 = o >> 4;       // cell within tile
        const int u   = o & 15;       // uint within cell (2 halves)
        const int cell = cellBase + cl2;
        if (cell < PLANE) {
            half2 h = __floats2half2_rn(tile[2 * u][cl2], tile[2 * u + 1][cl2]);
            ((unsigned int*)g2buf)[cell * 16 + u] = *(unsigned int*)&h;
        }
    }
}

__device__ __forceinline__ void bspline(float t, float& w0, float& w1, float& w2, float& w3) {
    float t2 = t * t, t3 = t2 * t;
    const float s = 1.0f / 6.0f;
    w0 = s * (1.0f - 3.0f * t + 3.0f * t2 - t3);
    w1 = s * (4.0f - 6.0f * t2 + 3.0f * t3);
    w2 = s * (1.0f + 3.0f * t + 3.0f * t2 - 3.0f * t3);
    w3 = s * t3;
}

__device__ __forceinline__ int clampi(int v) { return min(max(v, 0), GN - 1); }

__device__ __forceinline__ float normu(float v) {
    float n = 0.5f + 0.5f * (v / 5.0f);
    n = fminf(fmaxf(n, 0.0f), 1.0f);
    return n * (float)(GN - 1);
}

// Block = 256 threads = 8 warps, 64 points per block (8 per warp).
// Interp: warp-per-point. Lane: kk = lane>>3 (z-tap), ch = lane&7 (channel quad).
//   Per (i,j) tap: LDG.64 per lane, 256B/warp (4 z-cells x 32 fp16 channels).
//   Products accumulated packed in half2 (2 MACs/HFMA2), split chains, fp32
//   z-weighting + cross-lane reduce.
// Matmul: warp owns its 8 points x all 128 feats (4 feats/lane, 32 accum regs).
__global__ __launch_bounds__(256) void enc_kernel(
    const float* __restrict__ nb,
    const float* __restrict__ encw,
    const float* __restrict__ encb,
    float* __restrict__ out)
{
    __shared__ __align__(16) float ligT[GC][72];    // [channel][point-in-block]
    __shared__ __align__(16) float wS[GC][132];     // [k][feat]

    const int tid  = threadIdx.x;
    const int warp = tid >> 5;
    const int lane = tid & 31;
    const int p0   = blockIdx.x << 6;               // 64 points/block

    // Stage enc_w transposed: wS[k][f] = encw[f*32 + k]
    #pragma unroll
    for (int e = tid; e < GF * GC; e += 256) {
        wS[e & 31][e >> 5] = encw[e];
    }

    const int kk = lane >> 3;   // z-tap (0..3)
    const int ch = lane & 7;    // channel-quad (0..7)

    for (int pi = 0; pi < 8; pi++) {
        const int pp = (warp << 3) + pi;
        const int p  = p0 + pp;

        const float vx = nb[p * 3 + 0];
        const float vy = nb[p * 3 + 1];
        const float vz = nb[p * 3 + 2];

        const float ux = normu(vx), uy = normu(vy), uz = normu(vz);
        const float fbx = floorf(ux), fby = floorf(uy), fbz = floorf(uz);
        const float tx = ux - fbx, ty = uy - fby, tz = uz - fbz;
        const int ibx = (int)fbx, iby = (int)fby, ibz = (int)fbz;

        float wx0, wx1, wx2, wx3, wy0, wy1, wy2, wy3, wz0, wz1, wz2, wz3;
        bspline(tx, wx0, wx1, wx2, wx3);
        bspline(ty, wy0, wy1, wy2, wy3);
        bspline(tz, wz0, wz1, wz2, wz3);

        half2 hx[4], hy[4];
        hx[0] = __float2half2_rn(wx0); hx[1] = __float2half2_rn(wx1);
        hx[2] = __float2half2_rn(wx2); hx[3] = __float2half2_rn(wx3);
        hy[0] = __float2half2_rn(wy0); hy[1] = __float2half2_rn(wy1);
        hy[2] = __float2half2_rn(wy2); hy[3] = __float2half2_rn(wy3);

        const float myWz = (kk == 0) ? wz0 : (kk == 1) ? wz1 : (kk == 2) ? wz2 : wz3;
        const int  myIz  = clampi(ibz - 1 + kk);

        int ixs[4], iys[4];
        #pragma unroll
        for (int i = 0; i < 4; i++) {
            ixs[i] = clampi(ibx - 1 + i);
            iys[i] = clampi(iby - 1 + i);
        }

        const half2 hzero = __floats2half2_rn(0.0f, 0.0f);
        half2 a0 = hzero, a1 = hzero, b0 = hzero, b1 = hzero;

        #pragma unroll
        for (int i = 0; i < 4; i++) {
            const int rowx = ixs[i] * GN;
            #pragma unroll
            for (int j = 0; j < 4; j++) {
                const half2 w2 = __hmul2(hx[i], hy[j]);
                const uint2 vv = __ldg(&g2buf[(rowx + iys[j]) * (GN * 8) + myIz * 8 + ch]);
                const half2 v0 = *(const half2*)&vv.x;
                const half2 v1 = *(const half2*)&vv.y;
                if (j & 1) {
                    a1 = __hfma2(w2, v0, a1);
                    b1 = __hfma2(w2, v1, b1);
                } else {
                    a0 = __hfma2(w2, v0, a0);
                    b0 = __hfma2(w2, v1, b0);
                }
            }
        }

        const half2 sa = __hadd2(a0, a1);
        const half2 sb = __hadd2(b0, b1);
        const float2 fa = __half22float2(sa);
        const float2 fb = __half22float2(sb);
        float ax = fa.x * myWz;
        float ay = fa.y * myWz;
        float az = fb.x * myWz;
        float aw = fb.y * myWz;

        // Reduce over the 4 z-tap lane groups
        #pragma unroll
        for (int off = 8; off <= 16; off <<= 1) {
            ax += __shfl_xor_sync(0xffffffffu, ax, off);
            ay += __shfl_xor_sync(0xffffffffu, ay, off);
            az += __shfl_xor_sync(0xffffffffu, az, off);
            aw += __shfl_xor_sync(0xffffffffu, aw, off);
        }
        if (lane < 8) {
            ligT[ch * 4 + 0][pp] = ax;
            ligT[ch * 4 + 1][pp] = ay;
            ligT[ch * 4 + 2][pp] = az;
            ligT[ch * 4 + 3][pp] = aw;
        }
    }
    __syncthreads();

    // Matmul: warp handles points [warp*8, warp*8+8), feats lane*4..lane*4+4.
    const int pb = warp << 3;
    const float4 b4 = *(const float4*)(encb + lane * 4);
    float4 acc[8];
    #pragma unroll
    for (int pi = 0; pi < 8; pi++) acc[pi] = b4;

    #pragma unroll
    for (int k = 0; k < GC; k++) {
        const float4 wv  = *(const float4*)&wS[k][lane * 4];
        const float4 lgA = *(const float4*)&ligT[k][pb];
        const float4 lgB = *(const float4*)&ligT[k][pb + 4];
        const float lg[8] = {lgA.x, lgA.y, lgA.z, lgA.w, lgB.x, lgB.y, lgB.z, lgB.w};
        #pragma unroll
        for (int pi = 0; pi < 8; pi++) {
            acc[pi].x = fmaf(lg[pi], wv.x, acc[pi].x);
            acc[pi].y = fmaf(lg[pi], wv.y, acc[pi].y);
            acc[pi].z = fmaf(lg[pi], wv.z, acc[pi].z);
            acc[pi].w = fmaf(lg[pi], wv.w, acc[pi].w);
        }
    }

    float4* o4 = (float4*)out;
    const int rowbase = (p0 + pb) * (GF / 4) + lane;
    #pragma unroll
    for (int pi = 0; pi < 8; pi++) {
        o4[rowbase + pi * (GF / 4)] = acc[pi];
    }
}

extern "C" void kernel_launch(void* const* d_in, const int* in_sizes, int n_in,
                              void* d_out, int out_size) {
    const float* nb   = nullptr;
    const float* grid = nullptr;
    const float* encw = nullptr;
    const float* encb = nullptr;
    int nbatch = 131072;

    for (int i = 0; i < n_in; i++) {
        switch (in_sizes[i]) {
            case TOTAL:       grid = (const float*)d_in[i]; break;
            case GF * GC:     encw = (const float*)d_in[i]; break;
            case GF:          encb = (const float*)d_in[i]; break;
            default:
                nb = (const float*)d_in[i];
                nbatch = in_sizes[i] / 3;
                break;
        }
    }

    transpose_kernel<<<(PLANE + 63) / 64, 256>>>(grid);

    const int blocks = nbatch / 64;
    enc_kernel<<<blocks, 256>>>(nb, encw, encb, (float*)d_out);
}

// round 3
// speedup vs baseline: 1.3220x; 1.0856x over previous
#include <cuda_runtime.h>
#include <cuda_fp16.h>

#define GN     41
#define GC     32
#define GF     128
#define PLANE  (GN*GN*GN)        // 68921 cells
#define TOTAL  (PLANE*GC)        // 2205472 grid elements
#define NBDEF  131072

// Transposed fp16 grid: [x][y][z][c], c innermost. One cell = 32 halves = 64B.
__device__ __align__(128) uint2 g2buf[PLANE * 8];
// Per-point precomputed spline data, 64B/point:
//  [0]: float4 wx      [1]: float4 wz
//  [2]: {wy01(h2), wy23(h2), ixp, iyp}   [3].x: izp
__device__ __align__(128) uint4 wbuf[NBDEF * 4];

// ---------------- transpose + fp32->fp16 ----------------
__global__ __launch_bounds__(256) void transpose_kernel(const float* __restrict__ src) {
    __shared__ float tile[32][65];
    const int cellBase = blockIdx.x * 64;
    const int tid = threadIdx.x;
    const int c_l = tid >> 6, cl = tid & 63;
    #pragma unroll
    for (int cc = 0; cc < 8; cc++) {
        const int c = cc * 4 + c_l;
        const int cell = cellBase + cl;
        tile[c][cl] = (cell < PLANE) ? src[c * PLANE + cell] : 0.0f;
    }
    __syncthreads();
    #pragma unroll
    for (int it = 0; it < 4; it++) {
        const int o = it * 256 + tid;
        const int cl2 = o >> 4, u = o & 15;
        const int cell = cellBase + cl2;
        if (cell < PLANE) {
            half2 h = __floats2half2_rn(tile[2 * u][cl2], tile[2 * u + 1][cl2]);
            ((unsigned int*)g2buf)[cell * 16 + u] = *(unsigned int*)&h;
        }
    }
}

// ---------------- per-point weight precompute ----------------
__device__ __forceinline__ void bspline(float t, float& w0, float& w1, float& w2, float& w3) {
    float t2 = t * t, t3 = t2 * t;
    const float s = 1.0f / 6.0f;
    w0 = s * (1.0f - 3.0f * t + 3.0f * t2 - t3);
    w1 = s * (4.0f - 6.0f * t2 + 3.0f * t3);
    w2 = s * (1.0f + 3.0f * t + 3.0f * t2 - 3.0f * t3);
    w3 = s * t3;
}
__device__ __forceinline__ int clampi(int v) { return min(max(v, 0), GN - 1); }
__device__ __forceinline__ float normu(float v) {
    float n = 0.5f + 0.5f * (v / 5.0f);
    n = fminf(fmaxf(n, 0.0f), 1.0f);
    return n * (float)(GN - 1);
}

__global__ __launch_bounds__(256) void weight_kernel(const float* __restrict__ nb, int n) {
    const int p = blockIdx.x * 256 + threadIdx.x;
    if (p >= n) return;
    float w[3][4];
    int ib[3];
    #pragma unroll
    for (int d = 0; d < 3; d++) {
        const float u = normu(nb[3 * p + d]);
        const float fb = floorf(u);
        const float t = u - fb;
        ib[d] = (int)fb;
        bspline(t, w[d][0], w[d][1], w[d][2], w[d][3]);
    }
    unsigned ixp = 0, iyp = 0, izp = 0;
    #pragma unroll
    for (int i = 0; i < 4; i++) {
        ixp |= (unsigned)clampi(ib[0] - 1 + i) << (8 * i);
        iyp |= (unsigned)clampi(ib[1] - 1 + i) << (8 * i);
        izp |= (unsigned)clampi(ib[2] - 1 + i) << (8 * i);
    }
    uint4 u0, u1, u2, u3;
    u0.x = __float_as_uint(w[0][0]); u0.y = __float_as_uint(w[0][1]);
    u0.z = __float_as_uint(w[0][2]); u0.w = __float_as_uint(w[0][3]);
    u1.x = __float_as_uint(w[2][0]); u1.y = __float_as_uint(w[2][1]);
    u1.z = __float_as_uint(w[2][2]); u1.w = __float_as_uint(w[2][3]);
    half2 hy01 = __floats2half2_rn(w[1][0], w[1][1]);
    half2 hy23 = __floats2half2_rn(w[1][2], w[1][3]);
    u2.x = *(unsigned*)&hy01; u2.y = *(unsigned*)&hy23;
    u2.z = ixp; u2.w = iyp;
    u3.x = izp; u3.y = 0; u3.z = 0; u3.w = 0;
    wbuf[p * 4 + 0] = u0;
    wbuf[p * 4 + 1] = u1;
    wbuf[p * 4 + 2] = u2;
    wbuf[p * 4 + 3] = u3;
}

// ---------------- fused interp + tensor-core encoder ----------------
// Block = 256 threads = 8 warps, 64 points/block.
// Interp: warp-per-point (8 pts/warp). Lane: kk=lane>>3 (z-tap), ch=lane&7
//   (channel quad). Inner y-chain in half2 (len 4), x/z weighting in fp32,
//   cross-lane z reduction, result -> smem ligH[64][40] fp16 (padded rows,
//   LDSM conflict-free).
// Matmul: mma.sync m16n8k16 f16f16f32. warp (mt=warp&3, nt64=warp>>2) owns
//   rows [16mt,16mt+16) x cols [64nt64, +64). w staged fp16 [32][136].
__global__ __launch_bounds__(256) void enc_kernel(
    const float* __restrict__ encw,
    const float* __restrict__ encb,
    float* __restrict__ out)
{
    __shared__ __align__(16) __half ligH[64 * 40];
    __shared__ __align__(16) __half wH[32 * 136];

    const int tid  = threadIdx.x;
    const int warp = tid >> 5;
    const int lane = tid & 31;
    const int p0   = blockIdx.x << 6;

    // Stage enc_w fp16 transposed: wH[k][f] = encw[f*32+k]
    #pragma unroll
    for (int e = tid; e < GF * GC; e += 256) {
        wH[(e & 31) * 136 + (e >> 5)] = __float2half(encw[e]);
    }

    const int kk = lane >> 3;
    const int ch = lane & 7;

    for (int pi = 0; pi < 8; pi++) {
        const int pp = (warp << 3) + pi;
        const int p  = p0 + pp;

        const uint4 U0 = __ldg(&wbuf[p * 4 + 0]);
        const uint4 U1 = __ldg(&wbuf[p * 4 + 1]);
        const uint4 U2 = __ldg(&wbuf[p * 4 + 2]);
        const unsigned izp = __ldg((const unsigned*)wbuf + p * 16 + 12);

        const float wx0 = __uint_as_float(U0.x), wx1 = __uint_as_float(U0.y);
        const float wx2 = __uint_as_float(U0.z), wx3 = __uint_as_float(U0.w);
        const float wz0 = __uint_as_float(U1.x), wz1 = __uint_as_float(U1.y);
        const float wz2 = __uint_as_float(U1.z), wz3 = __uint_as_float(U1.w);
        const half2 hy01 = *(const half2*)&U2.x;
        const half2 hy23 = *(const half2*)&U2.y;
        const unsigned ixp = U2.z, iyp = U2.w;

        const half2 hyb0 = __low2half2(hy01), hyb1 = __high2half2(hy01);
        const half2 hyb2 = __low2half2(hy23), hyb3 = __high2half2(hy23);

        const float myWz = (kk & 2) ? ((kk & 1) ? wz3 : wz2)
                                    : ((kk & 1) ? wz1 : wz0);
        const int myIz = (izp >> (kk * 8)) & 255;
        const int zoff = myIz * 8 + ch;

        float ax = 0.0f, ay = 0.0f, az = 0.0f, aw = 0.0f;
        #pragma unroll
        for (int i = 0; i < 4; i++) {
            const int rowx = (int)((ixp >> (8 * i)) & 255) * GN;
            const half2 hz = __floats2half2_rn(0.0f, 0.0f);
            half2 ha = hz, hb = hz;
            #pragma unroll
            for (int j = 0; j < 4; j++) {
                const int iy = (int)((iyp >> (8 * j)) & 255);
                const uint2 vv = __ldg(&g2buf[(rowx + iy) * (GN * 8) + zoff]);
                const half2 v0 = *(const half2*)&vv.x;
                const half2 v1 = *(const half2*)&vv.y;
                const half2 hyj = (j == 0) ? hyb0 : (j == 1) ? hyb1 : (j == 2) ? hyb2 : hyb3;
                ha = __hfma2(hyj, v0, ha);
                hb = __hfma2(hyj, v1, hb);
            }
            const float wxi = (i == 0) ? wx0 : (i == 1) ? wx1 : (i == 2) ? wx2 : wx3;
            const float2 fa = __half22float2(ha);
            const float2 fb = __half22float2(hb);
            ax = fmaf(wxi, fa.x, ax);
            ay = fmaf(wxi, fa.y, ay);
            az = fmaf(wxi, fb.x, az);
            aw = fmaf(wxi, fb.y, aw);
        }
        ax *= myWz; ay *= myWz; az *= myWz; aw *= myWz;

        #pragma unroll
        for (int off = 8; off <= 16; off <<= 1) {
            ax += __shfl_xor_sync(0xffffffffu, ax, off);
            ay += __shfl_xor_sync(0xffffffffu, ay, off);
            az += __shfl_xor_sync(0xffffffffu, az, off);
            aw += __shfl_xor_sync(0xffffffffu, aw, off);
        }
        if (lane < 8) {
            half2 h01 = __floats2half2_rn(ax, ay);
            half2 h23 = __floats2half2_rn(az, aw);
            uint2 u;
            u.x = *(unsigned*)&h01;
            u.y = *(unsigned*)&h23;
            *(uint2*)&ligH[pp * 40 + ch * 4] = u;
        }
    }
    __syncthreads();

    // ---- tensor-core matmul ----
    const int mt = warp & 3, nt64 = warp >> 2;
    const int r  = lane >> 2;
    const int cq = (lane & 3) * 2;
    const int rbase = mt * 16;
    const int cbase = nt64 * 64;

    float c[8][4];
    #pragma unroll
    for (int nt = 0; nt < 8; nt++) {
        const float2 b2 = __ldg((const float2*)(encb + cbase + nt * 8 + cq));
        c[nt][0] = b2.x; c[nt][1] = b2.y;
        c[nt][2] = b2.x; c[nt][3] = b2.y;
    }

    #pragma unroll
    for (int ks = 0; ks < 2; ks++) {
        const int arow = rbase + (lane & 15);
        const int acol = ks * 16 + ((lane >> 4) << 3);
        unsigned aaddr = (unsigned)__cvta_generic_to_shared(&ligH[arow * 40 + acol]);
        unsigned a0, a1, a2, a3;
        asm volatile("ldmatrix.sync.aligned.m8n8.x4.shared.b16 {%0,%1,%2,%3}, [%4];"
                     : "=r"(a0), "=r"(a1), "=r"(a2), "=r"(a3) : "r"(aaddr));

        #pragma unroll
        for (int nt = 0; nt < 8; nt++) {
            const int brow = ks * 16 + (lane & 15);
            unsigned baddr = (unsigned)__cvta_generic_to_shared(&wH[brow * 136 + cbase + nt * 8]);
            unsigned b0, b1;
            asm volatile("ldmatrix.sync.aligned.m8n8.x2.trans.shared.b16 {%0,%1}, [%2];"
                         : "=r"(b0), "=r"(b1) : "r"(baddr));
            asm volatile("mma.sync.aligned.m16n8k16.row.col.f32.f16.f16.f32 "
                         "{%0,%1,%2,%3}, {%4,%5,%6,%7}, {%8,%9}, {%0,%1,%2,%3};"
                         : "+f"(c[nt][0]), "+f"(c[nt][1]), "+f"(c[nt][2]), "+f"(c[nt][3])
                         : "r"(a0), "r"(a1), "r"(a2), "r"(a3), "r"(b0), "r"(b1));
        }
    }

    const int grow = p0 + rbase + r;
    #pragma unroll
    for (int nt = 0; nt < 8; nt++) {
        const int col = cbase + nt * 8 + cq;
        *(float2*)(out + grow * GF + col)       = make_float2(c[nt][0], c[nt][1]);
        *(float2*)(out + (grow + 8) * GF + col) = make_float2(c[nt][2], c[nt][3]);
    }
}

extern "C" void kernel_launch(void* const* d_in, const int* in_sizes, int n_in,
                              void* d_out, int out_size) {
    const float* nb   = nullptr;
    const float* grid = nullptr;
    const float* encw = nullptr;
    const float* encb = nullptr;
    int nbatch = NBDEF;

    for (int i = 0; i < n_in; i++) {
        switch (in_sizes[i]) {
            case TOTAL:       grid = (const float*)d_in[i]; break;
            case GF * GC:     encw = (const float*)d_in[i]; break;
            case GF:          encb = (const float*)d_in[i]; break;
            default:
                nb = (const float*)d_in[i];
                nbatch = in_sizes[i] / 3;
                break;
        }
    }

    transpose_kernel<<<(PLANE + 63) / 64, 256>>>(grid);
    weight_kernel<<<(nbatch + 255) / 256, 256>>>(nb, nbatch);
    enc_kernel<<<nbatch / 64, 256>>>(encw, encb, (float*)d_out);
}

// round 4
// speedup vs baseline: 1.6652x; 1.2596x over previous
#include <cuda_runtime.h>
#include <cuda_fp16.h>

#define GN     41
#define GC     32
#define GF     128
#define PLANE  (GN*GN*GN)        // 68921 cells
#define TOTAL  (PLANE*GC)        // 2205472 grid elements

// Transposed fp16 grid: [x][y][z][c], c innermost. One cell = 32 halves = 64B.
__device__ __align__(128) uint2 g2buf[PLANE * 8];

// ---------------- transpose + fp32->fp16 (128 cells / block) ----------------
__global__ __launch_bounds__(256) void transpose_kernel(const float* __restrict__ src) {
    __shared__ float tile[32][65];
    const int tid = threadIdx.x;
    const int c_l = tid >> 6, cl = tid & 63;

    #pragma unroll
    for (int h = 0; h < 2; h++) {
        const int cellBase = blockIdx.x * 128 + h * 64;
        #pragma unroll
        for (int cc = 0; cc < 8; cc++) {
            const int c = cc * 4 + c_l;
            const int cell = cellBase + cl;
            tile[c][cl] = (cell < PLANE) ? src[c * PLANE + cell] : 0.0f;
        }
        __syncthreads();
        #pragma unroll
        for (int it = 0; it < 4; it++) {
            const int o = it * 256 + tid;
            const int cl2 = o >> 4, u = o & 15;
            const int cell = cellBase + cl2;
            if (cell < PLANE) {
                half2 hh = __floats2half2_rn(tile[2 * u][cl2], tile[2 * u + 1][cl2]);
                ((unsigned int*)g2buf)[cell * 16 + u] = *(unsigned int*)&hh;
            }
        }
        __syncthreads();
    }
}

// ---------------- helpers ----------------
__device__ __forceinline__ void bspline(float t, float& w0, float& w1, float& w2, float& w3) {
    float t2 = t * t, t3 = t2 * t;
    const float s = 1.0f / 6.0f;
    w0 = s * (1.0f - 3.0f * t + 3.0f * t2 - t3);
    w1 = s * (4.0f - 6.0f * t2 + 3.0f * t3);
    w2 = s * (1.0f + 3.0f * t + 3.0f * t2 - 3.0f * t3);
    w3 = s * t3;
}
__device__ __forceinline__ int clampi(int v) { return min(max(v, 0), GN - 1); }
__device__ __forceinline__ float normu(float v) {
    float n = 0.5f + 0.5f * (v / 5.0f);
    n = fminf(fmaxf(n, 0.0f), 1.0f);
    return n * (float)(GN - 1);
}

// ---------------- fused weights + interp + tensor-core encoder ----------------
// Block = 256 threads = 8 warps, 64 points/block, 4 CTAs/SM (<=64 regs).
// Phase 0: threads 0..63 compute their point's spline weights -> smem wS.
// Phase 1: warp-per-point interp (8 pts/warp), fp16 gather via LDG.64,
//          half2 y-chains, fp32 x/z weighting, shuffle z-reduction,
//          fp16 result -> ligH[64][40] (LDSM-friendly).
// Phase 2: mma.sync m16n8k16 f16f16f32; warp (m16 x n64) tile.
__global__ __launch_bounds__(256, 4) void enc_kernel(
    const float* __restrict__ nb,
    const float* __restrict__ encw,
    const float* __restrict__ encb,
    float* __restrict__ out)
{
    __shared__ __align__(16) __half ligH[64 * 40];
    __shared__ __align__(16) __half wH[32 * 136];
    __shared__ __align__(16) uint4 wS[64][4];

    const int tid  = threadIdx.x;
    const int warp = tid >> 5;
    const int lane = tid & 31;
    const int p0   = blockIdx.x << 6;

    // Stage enc_w fp16 transposed: wH[k][f] = encw[f*32+k]
    #pragma unroll
    for (int e = tid; e < GF * GC; e += 256) {
        wH[(e & 31) * 136 + (e >> 5)] = __float2half(encw[e]);
    }

    // Per-point spline weights into smem (one thread per point)
    if (tid < 64) {
        const int p = p0 + tid;
        float w[3][4];
        int ib[3];
        #pragma unroll
        for (int d = 0; d < 3; d++) {
            const float u = normu(nb[3 * p + d]);
            const float fb = floorf(u);
            const float t = u - fb;
            ib[d] = (int)fb;
            bspline(t, w[d][0], w[d][1], w[d][2], w[d][3]);
        }
        unsigned ixp = 0, iyp = 0, izp = 0;
        #pragma unroll
        for (int i = 0; i < 4; i++) {
            ixp |= (unsigned)clampi(ib[0] - 1 + i) << (8 * i);
            iyp |= (unsigned)clampi(ib[1] - 1 + i) << (8 * i);
            izp |= (unsigned)clampi(ib[2] - 1 + i) << (8 * i);
        }
        uint4 u0, u1, u2, u3;
        u0.x = __float_as_uint(w[0][0]); u0.y = __float_as_uint(w[0][1]);
        u0.z = __float_as_uint(w[0][2]); u0.w = __float_as_uint(w[0][3]);
        u1.x = __float_as_uint(w[2][0]); u1.y = __float_as_uint(w[2][1]);
        u1.z = __float_as_uint(w[2][2]); u1.w = __float_as_uint(w[2][3]);
        half2 hy01 = __floats2half2_rn(w[1][0], w[1][1]);
        half2 hy23 = __floats2half2_rn(w[1][2], w[1][3]);
        u2.x = *(unsigned*)&hy01; u2.y = *(unsigned*)&hy23;
        u2.z = ixp; u2.w = iyp;
        u3.x = izp; u3.y = 0; u3.z = 0; u3.w = 0;
        wS[tid][0] = u0; wS[tid][1] = u1; wS[tid][2] = u2; wS[tid][3] = u3;
    }
    __syncthreads();

    const int kk = lane >> 3;
    const int ch = lane & 7;

    #pragma unroll 2
    for (int pi = 0; pi < 8; pi++) {
        const int pp = (warp << 3) + pi;

        const uint4 U0 = wS[pp][0];
        const uint4 U1 = wS[pp][1];
        const uint4 U2 = wS[pp][2];
        const unsigned izp = wS[pp][3].x;

        const float wx0 = __uint_as_float(U0.x), wx1 = __uint_as_float(U0.y);
        const float wx2 = __uint_as_float(U0.z), wx3 = __uint_as_float(U0.w);
        const float wz0 = __uint_as_float(U1.x), wz1 = __uint_as_float(U1.y);
        const float wz2 = __uint_as_float(U1.z), wz3 = __uint_as_float(U1.w);
        const half2 hy01 = *(const half2*)&U2.x;
        const half2 hy23 = *(const half2*)&U2.y;
        const unsigned ixp = U2.z, iyp = U2.w;

        const half2 hyb0 = __low2half2(hy01), hyb1 = __high2half2(hy01);
        const half2 hyb2 = __low2half2(hy23), hyb3 = __high2half2(hy23);

        const float myWz = (kk & 2) ? ((kk & 1) ? wz3 : wz2)
                                    : ((kk & 1) ? wz1 : wz0);
        const int myIz = (izp >> (kk * 8)) & 255;
        const int zoff = myIz * 8 + ch;

        float ax = 0.0f, ay = 0.0f, az = 0.0f, aw = 0.0f;
        #pragma unroll
        for (int i = 0; i < 4; i++) {
            const int rowx = (int)((ixp >> (8 * i)) & 255) * GN;
            const half2 hz = __floats2half2_rn(0.0f, 0.0f);
            half2 ha = hz, hb = hz;
            #pragma unroll
            for (int j = 0; j < 4; j++) {
                const int iy = (int)((iyp >> (8 * j)) & 255);
                const uint2 vv = __ldg(&g2buf[(rowx + iy) * (GN * 8) + zoff]);
                const half2 v0 = *(const half2*)&vv.x;
                const half2 v1 = *(const half2*)&vv.y;
                const half2 hyj = (j == 0) ? hyb0 : (j == 1) ? hyb1 : (j == 2) ? hyb2 : hyb3;
                ha = __hfma2(hyj, v0, ha);
                hb = __hfma2(hyj, v1, hb);
            }
            const float wxi = (i == 0) ? wx0 : (i == 1) ? wx1 : (i == 2) ? wx2 : wx3;
            const float2 fa = __half22float2(ha);
            const float2 fb = __half22float2(hb);
            ax = fmaf(wxi, fa.x, ax);
            ay = fmaf(wxi, fa.y, ay);
            az = fmaf(wxi, fb.x, az);
            aw = fmaf(wxi, fb.y, aw);
        }
        ax *= myWz; ay *= myWz; az *= myWz; aw *= myWz;

        #pragma unroll
        for (int off = 8; off <= 16; off <<= 1) {
            ax += __shfl_xor_sync(0xffffffffu, ax, off);
            ay += __shfl_xor_sync(0xffffffffu, ay, off);
            az += __shfl_xor_sync(0xffffffffu, az, off);
            aw += __shfl_xor_sync(0xffffffffu, aw, off);
        }
        if (lane < 8) {
            half2 h01 = __floats2half2_rn(ax, ay);
            half2 h23 = __floats2half2_rn(az, aw);
            uint2 u;
            u.x = *(unsigned*)&h01;
            u.y = *(unsigned*)&h23;
            *(uint2*)&ligH[pp * 40 + ch * 4] = u;
        }
    }
    __syncthreads();

    // ---- tensor-core matmul ----
    const int mt = warp & 3, nt64 = warp >> 2;
    const int r  = lane >> 2;
    const int cq = (lane & 3) * 2;
    const int rbase = mt * 16;
    const int cbase = nt64 * 64;

    float c[8][4];
    #pragma unroll
    for (int nt = 0; nt < 8; nt++) {
        const float2 b2 = __ldg((const float2*)(encb + cbase + nt * 8 + cq));
        c[nt][0] = b2.x; c[nt][1] = b2.y;
        c[nt][2] = b2.x; c[nt][3] = b2.y;
    }

    #pragma unroll
    for (int ks = 0; ks < 2; ks++) {
        const int arow = rbase + (lane & 15);
        const int acol = ks * 16 + ((lane >> 4) << 3);
        unsigned aaddr = (unsigned)__cvta_generic_to_shared(&ligH[arow * 40 + acol]);
        unsigned a0, a1, a2, a3;
        asm volatile("ldmatrix.sync.aligned.m8n8.x4.shared.b16 {%0,%1,%2,%3}, [%4];"
                     : "=r"(a0), "=r"(a1), "=r"(a2), "=r"(a3) : "r"(aaddr));

        #pragma unroll
        for (int nt = 0; nt < 8; nt++) {
            const int brow = ks * 16 + (lane & 15);
            unsigned baddr = (unsigned)__cvta_generic_to_shared(&wH[brow * 136 + cbase + nt * 8]);
            unsigned b0, b1;
            asm volatile("ldmatrix.sync.aligned.m8n8.x2.trans.shared.b16 {%0,%1}, [%2];"
                         : "=r"(b0), "=r"(b1) : "r"(baddr));
            asm volatile("mma.sync.aligned.m16n8k16.row.col.f32.f16.f16.f32 "
                         "{%0,%1,%2,%3}, {%4,%5,%6,%7}, {%8,%9}, {%0,%1,%2,%3};"
                         : "+f"(c[nt][0]), "+f"(c[nt][1]), "+f"(c[nt][2]), "+f"(c[nt][3])
                         : "r"(a0), "r"(a1), "r"(a2), "r"(a3), "r"(b0), "r"(b1));
        }
    }

    const int grow = p0 + rbase + r;
    #pragma unroll
    for (int nt = 0; nt < 8; nt++) {
        const int col = cbase + nt * 8 + cq;
        *(float2*)(out + grow * GF + col)       = make_float2(c[nt][0], c[nt][1]);
        *(float2*)(out + (grow + 8) * GF + col) = make_float2(c[nt][2], c[nt][3]);
    }
}

extern "C" void kernel_launch(void* const* d_in, const int* in_sizes, int n_in,
                              void* d_out, int out_size) {
    const float* nb   = nullptr;
    const float* grid = nullptr;
    const float* encw = nullptr;
    const float* encb = nullptr;
    int nbatch = 131072;

    for (int i = 0; i < n_in; i++) {
        switch (in_sizes[i]) {
            case TOTAL:       grid = (const float*)d_in[i]; break;
            case GF * GC:     encw = (const float*)d_in[i]; break;
            case GF:          encb = (const float*)d_in[i]; break;
            default:
                nb = (const float*)d_in[i];
                nbatch = in_sizes[i] / 3;
                break;
        }
    }

    transpose_kernel<<<(PLANE + 127) / 128, 256>>>(grid);
    enc_kernel<<<nbatch / 64, 256>>>(nb, encw, encb, (float*)d_out);
}

// round 5
// speedup vs baseline: 1.7303x; 1.0391x over previous
#include <cuda_runtime.h>
#include <cuda_fp16.h>

#define GN     41
#define GC     32
#define GF     128
#define PLANE  (GN*GN*GN)        // 68921 cells
#define TOTAL  (PLANE*GC)        // 2205472 grid elements

// Transposed fp16 grid: [x][y][z][c], c innermost. One cell = 32 halves = 64B.
__device__ __align__(128) uint2 g2buf[PLANE * 8];

// ---------------- transpose + fp32->fp16 (128 cells / block) ----------------
__global__ __launch_bounds__(256) void transpose_kernel(const float* __restrict__ src) {
    __shared__ float tile[32][65];
    const int tid = threadIdx.x;
    const int c_l = tid >> 6, cl = tid & 63;

    #pragma unroll
    for (int h = 0; h < 2; h++) {
        const int cellBase = blockIdx.x * 128 + h * 64;
        #pragma unroll
        for (int cc = 0; cc < 8; cc++) {
            const int c = cc * 4 + c_l;
            const int cell = cellBase + cl;
            tile[c][cl] = (cell < PLANE) ? src[c * PLANE + cell] : 0.0f;
        }
        __syncthreads();
        #pragma unroll
        for (int it = 0; it < 4; it++) {
            const int o = it * 256 + tid;
            const int cl2 = o >> 4, u = o & 15;
            const int cell = cellBase + cl2;
            if (cell < PLANE) {
                half2 hh = __floats2half2_rn(tile[2 * u][cl2], tile[2 * u + 1][cl2]);
                ((unsigned int*)g2buf)[cell * 16 + u] = *(unsigned int*)&hh;
            }
        }
        __syncthreads();
    }
}

// ---------------- helpers ----------------
__device__ __forceinline__ void bspline(float t, float& w0, float& w1, float& w2, float& w3) {
    float t2 = t * t, t3 = t2 * t;
    const float s = 1.0f / 6.0f;
    w0 = s * (1.0f - 3.0f * t + 3.0f * t2 - t3);
    w1 = s * (4.0f - 6.0f * t2 + 3.0f * t3);
    w2 = s * (1.0f + 3.0f * t + 3.0f * t2 - 3.0f * t3);
    w3 = s * t3;
}
__device__ __forceinline__ int clampi(int v) { return min(max(v, 0), GN - 1); }
__device__ __forceinline__ float normu(float v) {
    float n = 0.5f + 0.5f * (v / 5.0f);
    n = fminf(fmaxf(n, 0.0f), 1.0f);
    return n * (float)(GN - 1);
}

// ---------------- fused weights + interp + tensor-core encoder ----------------
// Block = 256 threads = 8 warps, 64 points/block, 4 CTAs/SM.
// Smem regions (aliased; epilogue buffer reuses everything after mma):
//   ligH: 64*40 half   = 5120B   @0
//   wH:   32*136 half  = 8704B   @5120
//   wS:   64*4 uint4   = 4096B   @13824
//   obuf: 32*132 float = 16896B  @0 (epilogue only)
// Interp: 2 points/warp. lane = halfp*16 + zt*4 + chq.
//   Per (i,j) tap one LDG.128 serves both points (8 ch/lane, 4 z-taps spread
//   over lanes). half2 y-chains (len 4), fp32 x/z weighting, 2-stage shuffle
//   z-reduce, fp16 write to ligH.
// Matmul: mma.sync m16n8k16 f16f16f32 (warp = m16 x n64 tile).
// Epilogue: fragments -> obuf (2 half-tile passes) -> coalesced STG.128.
__global__ __launch_bounds__(256, 4) void enc_kernel(
    const float* __restrict__ nb,
    const float* __restrict__ encw,
    const float* __restrict__ encb,
    float* __restrict__ out)
{
    __shared__ __align__(16) char smraw[17920];
    __half* ligH = (__half*)smraw;
    __half* wH   = (__half*)(smraw + 5120);
    uint4 (*wS)[4] = (uint4(*)[4])(smraw + 13824);
    float* obuf  = (float*)smraw;

    const int tid  = threadIdx.x;
    const int warp = tid >> 5;
    const int lane = tid & 31;
    const int p0   = blockIdx.x << 6;

    // Stage enc_w fp16 transposed: wH[k*136+f] = encw[f*32+k]
    #pragma unroll
    for (int e = tid; e < GF * GC; e += 256) {
        wH[(e & 31) * 136 + (e >> 5)] = __float2half(encw[e]);
    }

    // Per-point spline weights into smem (one thread per point)
    if (tid < 64) {
        const int p = p0 + tid;
        float w[3][4];
        int ib[3];
        #pragma unroll
        for (int d = 0; d < 3; d++) {
            const float u = normu(nb[3 * p + d]);
            const float fb = floorf(u);
            const float t = u - fb;
            ib[d] = (int)fb;
            bspline(t, w[d][0], w[d][1], w[d][2], w[d][3]);
        }
        unsigned ixp = 0, iyp = 0, izp = 0;
        #pragma unroll
        for (int i = 0; i < 4; i++) {
            ixp |= (unsigned)clampi(ib[0] - 1 + i) << (8 * i);
            iyp |= (unsigned)clampi(ib[1] - 1 + i) << (8 * i);
            izp |= (unsigned)clampi(ib[2] - 1 + i) << (8 * i);
        }
        uint4 u0, u1, u2, u3;
        u0.x = __float_as_uint(w[0][0]); u0.y = __float_as_uint(w[0][1]);
        u0.z = __float_as_uint(w[0][2]); u0.w = __float_as_uint(w[0][3]);
        u1.x = __float_as_uint(w[2][0]); u1.y = __float_as_uint(w[2][1]);
        u1.z = __float_as_uint(w[2][2]); u1.w = __float_as_uint(w[2][3]);
        half2 hy01 = __floats2half2_rn(w[1][0], w[1][1]);
        half2 hy23 = __floats2half2_rn(w[1][2], w[1][3]);
        u2.x = *(unsigned*)&hy01; u2.y = *(unsigned*)&hy23;
        u2.z = ixp; u2.w = iyp;
        u3.x = izp; u3.y = 0; u3.z = 0; u3.w = 0;
        wS[tid][0] = u0; wS[tid][1] = u1; wS[tid][2] = u2; wS[tid][3] = u3;
    }
    __syncthreads();

    // ---- interp: 2 points per warp ----
    const int halfp = lane >> 4;     // which point of the pair
    const int l16   = lane & 15;
    const int zt    = l16 >> 2;      // z-tap 0..3
    const int chq   = l16 & 3;       // channel octet (8 ch as uint4)
    const uint4* __restrict__ g4 = (const uint4*)g2buf;

    #pragma unroll 2
    for (int pr = 0; pr < 4; pr++) {
        const int pp = (warp << 3) + pr * 2 + halfp;

        const uint4 U0 = wS[pp][0];
        const uint4 U1 = wS[pp][1];
        const uint4 U2 = wS[pp][2];
        const unsigned izp = wS[pp][3].x;

        const float wx0 = __uint_as_float(U0.x), wx1 = __uint_as_float(U0.y);
        const float wx2 = __uint_as_float(U0.z), wx3 = __uint_as_float(U0.w);
        const half2 hy01 = *(const half2*)&U2.x;
        const half2 hy23 = *(const half2*)&U2.y;
        const half2 hyb0 = __low2half2(hy01), hyb1 = __high2half2(hy01);
        const half2 hyb2 = __low2half2(hy23), hyb3 = __high2half2(hy23);
        const unsigned ixp = U2.z, iyp = U2.w;

        const float wzv = __uint_as_float(
            (zt == 0) ? U1.x : (zt == 1) ? U1.y : (zt == 2) ? U1.z : U1.w);
        const int izv = (int)((izp >> (8 * zt)) & 255);
        const int zq  = izv * 4 + chq;

        int xoff[4], yoff[4];
        #pragma unroll
        for (int i = 0; i < 4; i++) {
            xoff[i] = (int)((ixp >> (8 * i)) & 255) * (GN * GN * 4);
            yoff[i] = (int)((iyp >> (8 * i)) & 255) * (GN * 4);
        }

        float xa0 = 0.f, xa1 = 0.f, xa2 = 0.f, xa3 = 0.f;
        float xa4 = 0.f, xa5 = 0.f, xa6 = 0.f, xa7 = 0.f;

        #pragma unroll
        for (int i = 0; i < 4; i++) {
            const half2 hz = __floats2half2_rn(0.f, 0.f);
            half2 j0 = hz, j1 = hz, j2 = hz, j3 = hz;
            #pragma unroll
            for (int j = 0; j < 4; j++) {
                const uint4 v = __ldg(&g4[xoff[i] + yoff[j] + zq]);
                const half2 hyj = (j == 0) ? hyb0 : (j == 1) ? hyb1 : (j == 2) ? hyb2 : hyb3;
                j0 = __hfma2(hyj, *(const half2*)&v.x, j0);
                j1 = __hfma2(hyj, *(const half2*)&v.y, j1);
                j2 = __hfma2(hyj, *(const half2*)&v.z, j2);
                j3 = __hfma2(hyj, *(const half2*)&v.w, j3);
            }
            const float wxi = (i == 0) ? wx0 : (i == 1) ? wx1 : (i == 2) ? wx2 : wx3;
            xa0 = fmaf(wxi, __low2float(j0),  xa0);
            xa1 = fmaf(wxi, __high2float(j0), xa1);
            xa2 = fmaf(wxi, __low2float(j1),  xa2);
            xa3 = fmaf(wxi, __high2float(j1), xa3);
            xa4 = fmaf(wxi, __low2float(j2),  xa4);
            xa5 = fmaf(wxi, __high2float(j2), xa5);
            xa6 = fmaf(wxi, __low2float(j3),  xa6);
            xa7 = fmaf(wxi, __high2float(j3), xa7);
        }

        xa0 *= wzv; xa1 *= wzv; xa2 *= wzv; xa3 *= wzv;
        xa4 *= wzv; xa5 *= wzv; xa6 *= wzv; xa7 *= wzv;

        #pragma unroll
        for (int off = 4; off <= 8; off <<= 1) {
            xa0 += __shfl_xor_sync(0xffffffffu, xa0, off);
            xa1 += __shfl_xor_sync(0xffffffffu, xa1, off);
            xa2 += __shfl_xor_sync(0xffffffffu, xa2, off);
            xa3 += __shfl_xor_sync(0xffffffffu, xa3, off);
            xa4 += __shfl_xor_sync(0xffffffffu, xa4, off);
            xa5 += __shfl_xor_sync(0xffffffffu, xa5, off);
            xa6 += __shfl_xor_sync(0xffffffffu, xa6, off);
            xa7 += __shfl_xor_sync(0xffffffffu, xa7, off);
        }

        if (zt == 0) {
            half2 h0 = __floats2half2_rn(xa0, xa1);
            half2 h1 = __floats2half2_rn(xa2, xa3);
            half2 h2 = __floats2half2_rn(xa4, xa5);
            half2 h3 = __floats2half2_rn(xa6, xa7);
            uint4 u;
            u.x = *(unsigned*)&h0; u.y = *(unsigned*)&h1;
            u.z = *(unsigned*)&h2; u.w = *(unsigned*)&h3;
            *(uint4*)&ligH[pp * 40 + chq * 8] = u;
        }
    }
    __syncthreads();

    // ---- tensor-core matmul ----
    const int mt = warp & 3, nt64 = warp >> 2;
    const int r  = lane >> 2;
    const int cq = (lane & 3) * 2;
    const int rbase = mt * 16;
    const int cbase = nt64 * 64;

    float c[8][4];
    #pragma unroll
    for (int nt = 0; nt < 8; nt++) {
        const float2 b2 = __ldg((const float2*)(encb + cbase + nt * 8 + cq));
        c[nt][0] = b2.x; c[nt][1] = b2.y;
        c[nt][2] = b2.x; c[nt][3] = b2.y;
    }

    #pragma unroll
    for (int ks = 0; ks < 2; ks++) {
        const int arow = rbase + (lane & 15);
        const int acol = ks * 16 + ((lane >> 4) << 3);
        unsigned aaddr = (unsigned)__cvta_generic_to_shared(&ligH[arow * 40 + acol]);
        unsigned a0, a1, a2, a3;
        asm volatile("ldmatrix.sync.aligned.m8n8.x4.shared.b16 {%0,%1,%2,%3}, [%4];"
                     : "=r"(a0), "=r"(a1), "=r"(a2), "=r"(a3) : "r"(aaddr));

        #pragma unroll
        for (int nt = 0; nt < 8; nt++) {
            const int brow = ks * 16 + (lane & 15);
            unsigned baddr = (unsigned)__cvta_generic_to_shared(&wH[brow * 136 + cbase + nt * 8]);
            unsigned b0, b1;
            asm volatile("ldmatrix.sync.aligned.m8n8.x2.trans.shared.b16 {%0,%1}, [%2];"
                         : "=r"(b0), "=r"(b1) : "r"(baddr));
            asm volatile("mma.sync.aligned.m16n8k16.row.col.f32.f16.f16.f32 "
                         "{%0,%1,%2,%3}, {%4,%5,%6,%7}, {%8,%9}, {%0,%1,%2,%3};"
                         : "+f"(c[nt][0]), "+f"(c[nt][1]), "+f"(c[nt][2]), "+f"(c[nt][3])
                         : "r"(a0), "r"(a1), "r"(a2), "r"(a3), "r"(b0), "r"(b1));
        }
    }
    __syncthreads();   // all mma reads of ligH/wH done; obuf may alias them

    // ---- coalesced epilogue: 2 half-tile passes through smem ----
    #pragma unroll
    for (int h = 0; h < 2; h++) {
        if ((mt >> 1) == h) {
            const int rl = ((mt & 1) << 4) + r;
            #pragma unroll
            for (int nt = 0; nt < 8; nt++) {
                const int col = cbase + nt * 8 + cq;
                *(float2*)&obuf[rl * 132 + col]       = make_float2(c[nt][0], c[nt][1]);
                *(float2*)&obuf[(rl + 8) * 132 + col] = make_float2(c[nt][2], c[nt][3]);
            }
        }
        __syncthreads();
        const float4* b4 = (const float4*)obuf;
        float4* o4 = (float4*)out;
        #pragma unroll
        for (int q = 0; q < 4; q++) {
            const int f  = q * 256 + tid;
            const int rr = f >> 5, c4 = f & 31;
            o4[(p0 + h * 32 + rr) * 32 + c4] = b4[rr * 33 + c4];
        }
        __syncthreads();
    }
}

extern "C" void kernel_launch(void* const* d_in, const int* in_sizes, int n_in,
                              void* d_out, int out_size) {
    const float* nb   = nullptr;
    const float* grid = nullptr;
    const float* encw = nullptr;
    const float* encb = nullptr;
    int nbatch = 131072;

    for (int i = 0; i < n_in; i++) {
        switch (in_sizes[i]) {
            case TOTAL:       grid = (const float*)d_in[i]; break;
            case GF * GC:     encw = (const float*)d_in[i]; break;
            case GF:          encb = (const float*)d_in[i]; break;
            default:
                nb = (const float*)d_in[i];
                nbatch = in_sizes[i] / 3;
                break;
        }
    }

    transpose_kernel<<<(PLANE + 127) / 128, 256>>>(grid);
    enc_kernel<<<nbatch / 64, 256>>>(nb, encw, encb, (float*)d_out);
}